// round 1
// baseline (speedup 1.0000x reference)
#include <cuda_runtime.h>
#include <math.h>

// ---------------- problem constants ----------------
#define NN   325
#define HID  64
#define BB   64
#define NH   (NN*HID)          // 20800
#define BNH  ((long)BB*NH)     // 1,331,200
#define MAXCB (128*64)         // 8192

// ---------------- device scratch (no allocations allowed) ----------------
__device__ float g_S[2][NN*NN];
__device__ float g_rsum[NN];
__device__ float g_csum[NN];
__device__ float g_mats[5L * NN * MAXCB];   // 5 Chebyshev mats, layout [m][n][c][b], b fastest
__device__ float g_h[2][BNH];               // per-layer hidden state [B, N*HID]
__device__ float g_r[BNH];
__device__ float g_u[BNH];

// ---------------- support prep ----------------
__global__ void k_sums(const float* __restrict__ adj) {
    __shared__ float sr[128], sc[128];
    int i = blockIdx.x;
    float rs = 0.f, cs = 0.f;
    for (int j = threadIdx.x; j < NN; j += 128) {
        rs += adj[i*NN + j];   // row sum of row i
        cs += adj[j*NN + i];   // col sum of col i
    }
    sr[threadIdx.x] = rs; sc[threadIdx.x] = cs;
    __syncthreads();
    for (int o = 64; o; o >>= 1) {
        if (threadIdx.x < o) {
            sr[threadIdx.x] += sr[threadIdx.x + o];
            sc[threadIdx.x] += sc[threadIdx.x + o];
        }
        __syncthreads();
    }
    if (threadIdx.x == 0) { g_rsum[i] = sr[0]; g_csum[i] = sc[0]; }
}

__global__ void k_supports(const float* __restrict__ adj) {
    int idx = blockIdx.x * blockDim.x + threadIdx.x;
    if (idx >= NN*NN) return;
    int i = idx / NN, j = idx - i*NN;
    // S1[i,j] = adj[j,i] / rowsum_j ;  S2[i,j] = adj[i,j] / colsum_j
    g_S[0][idx] = adj[j*NN + i] / g_rsum[j];
    g_S[1][idx] = adj[idx]      / g_csum[j];
}

__global__ void k_copyinit(const float* __restrict__ s) {
    long i = (long)blockIdx.x * blockDim.x + threadIdx.x;
    if (i < 2*BNH) (&g_h[0][0])[i] = s[i];
}

__global__ void k_zero(float* __restrict__ out) {
    int i = blockIdx.x * blockDim.x + threadIdx.x;
    if (i < NH) out[i] = 0.f;
}

// ---------------- build mats[0] = [N, C, B] (x ++ h  or  x ++ r*h) ----------------
__global__ void k_build(const float* __restrict__ x_ext, int layer, int use_r,
                        int in_dim, int C) {
    int idx = blockIdx.x * blockDim.x + threadIdx.x;
    int total = NN * C * BB;
    if (idx >= total) return;
    int b = idx & 63;
    int c = (idx >> 6) % C;
    int n = idx / (C * 64);
    float v;
    if (c < in_dim) {
        const float* x = (layer == 0) ? x_ext : g_h[0];
        v = x[(b*NN + n)*in_dim + c];
    } else {
        int k = c - in_dim;
        long off = (long)b*NH + n*HID + k;
        v = g_h[layer][off];
        if (use_r) v *= g_r[off];
    }
    g_mats[idx] = v;   // idx == n*C*64 + c*64 + b
}

// ---------------- S @ X  (both supports via blockIdx.z; Chebyshev epilogue fused) ----
// BM=64, BN=128, BK=16, 256 threads, 8x4 accum per thread
template<bool CHEB>
__global__ __launch_bounds__(256) void k_smul(int CB) {
    const int z = blockIdx.z;
    const long MS = (long)NN * CB;
    const float* __restrict__ S = g_S[z];
    const float* __restrict__ X = CHEB ? (g_mats + (1 + 2*z)*MS) : g_mats;
    float* __restrict__ Y = g_mats + (CHEB ? (2 + 2*z) : (1 + 2*z))*MS;

    const int m0 = blockIdx.y * 64;
    const int n0 = blockIdx.x * 128;
    const int tid = threadIdx.x;

    __shared__ float As[16][64];
    __shared__ float Bs[16][128];

    float acc[8][4];
#pragma unroll
    for (int i = 0; i < 8; i++)
#pragma unroll
        for (int j = 0; j < 4; j++) acc[i][j] = 0.f;

    const int rA = tid >> 2, kq = (tid & 3) << 2;
    const int rB = tid >> 4, cB = (tid & 15) << 3;
    const int trow = tid >> 5, tcol = tid & 31;

    for (int kt = 0; kt < NN; kt += 16) {
        // --- load S tile (transposed into As[k][m]) ---
        int gmA = m0 + rA;
#pragma unroll
        for (int kk = 0; kk < 4; kk++) {
            int gk = kt + kq + kk;
            As[kq + kk][rA] = (gmA < NN && gk < NN) ? S[gmA*NN + gk] : 0.f;
        }
        // --- load X tile ---
        int gkB = kt + rB;
        float4 b0 = make_float4(0.f,0.f,0.f,0.f), b1 = b0;
        if (gkB < NN && (n0 + cB) < CB) {
            const float* src = X + (long)gkB*CB + n0 + cB;
            b0 = *(const float4*)src;
            b1 = *(const float4*)(src + 4);
        }
        *(float4*)&Bs[rB][cB]     = b0;
        *(float4*)&Bs[rB][cB + 4] = b1;
        __syncthreads();

#pragma unroll
        for (int k = 0; k < 16; k++) {
            float a[8], w[4];
#pragma unroll
            for (int i = 0; i < 8; i++) a[i] = As[k][trow*8 + i];
#pragma unroll
            for (int j = 0; j < 4; j++) w[j] = Bs[k][tcol*4 + j];
#pragma unroll
            for (int i = 0; i < 8; i++)
#pragma unroll
                for (int j = 0; j < 4; j++)
                    acc[i][j] += a[i] * w[j];
        }
        __syncthreads();
    }

#pragma unroll
    for (int i = 0; i < 8; i++) {
        int gm = m0 + trow*8 + i;
        if (gm >= NN) continue;
#pragma unroll
        for (int j = 0; j < 4; j++) {
            int gn = n0 + tcol*4 + j;
            if (gn >= CB) continue;
            float v = acc[i][j];
            if (CHEB) v = 2.f*v - g_mats[(long)gm*CB + gn];
            Y[(long)gm*CB + gn] = v;
        }
    }
}

// ---------------- per-node GEMM2: xs @ W + b, fused activations ----------------
// Block = one node n (+ blockIdx.y halves the 128 gate outputs).
// xs[(b,n), c*5+m] = g_mats[m][n][c][b]  -> contiguous in b.
template<bool GATE>
__global__ __launch_bounds__(256) void k_gemm2(int C, const float* __restrict__ W,
                                               const float* __restrict__ bias, int layer) {
    const int n = blockIdx.x;
    const int ocol0 = GATE ? blockIdx.y * 64 : 0;
    const int WCOLS = GATE ? 128 : 64;
    const int CB = C * 64;
    const long MS = (long)NN * CB;
    const int tid = threadIdx.x;

    __shared__ float Axs[20][64];
    __shared__ float Ws[20][64];

    float acc[4][4];
#pragma unroll
    for (int i = 0; i < 4; i++)
#pragma unroll
        for (int j = 0; j < 4; j++) acc[i][j] = 0.f;

    const int trow = tid >> 4;   // 0..15 -> b rows trow*4..+4
    const int tcol = tid & 15;   // 0..15 -> o cols tcol*4..+4

    const int ntiles = (C + 3) >> 2;
    for (int ct = 0; ct < ntiles; ct++) {
        int c0 = ct * 4;
#pragma unroll
        for (int l = 0; l < 5; l++) {
            int idx = tid + l * 256;       // 0..1279
            int lo = idx & 63;
            int km = idx >> 6;             // 0..19
            int cq = km / 5;
            int m  = km - cq * 5;
            int c  = c0 + cq;
            bool ok = (c < C);
            Axs[km][lo] = ok ? g_mats[m*MS + (long)n*CB + c*64 + lo] : 0.f;
            Ws[km][lo]  = ok ? W[(c*5 + m)*WCOLS + ocol0 + lo] : 0.f;
        }
        __syncthreads();
#pragma unroll
        for (int km = 0; km < 20; km++) {
            float a[4], w[4];
#pragma unroll
            for (int i = 0; i < 4; i++) a[i] = Axs[km][trow*4 + i];
#pragma unroll
            for (int j = 0; j < 4; j++) w[j] = Ws[km][tcol*4 + j];
#pragma unroll
            for (int i = 0; i < 4; i++)
#pragma unroll
                for (int j = 0; j < 4; j++)
                    acc[i][j] += a[i] * w[j];
        }
        __syncthreads();
    }

#pragma unroll
    for (int i = 0; i < 4; i++) {
        int b = trow*4 + i;
#pragma unroll
        for (int j = 0; j < 4; j++) {
            int ol = tcol*4 + j;                 // local out col (0..63)
            float v = acc[i][j] + bias[ocol0 + ol];
            long off = (long)b*NH + n*HID + ol;
            if (GATE) {
                v = 1.f / (1.f + expf(-v));
                if (blockIdx.y == 0) g_r[off] = v; else g_u[off] = v;
            } else {
                float cv = tanhf(v);
                float u = g_u[off];
                float h = g_h[layer][off];
                g_h[layer][off] = u*h + (1.f - u)*cv;
            }
        }
    }
}

// ---------------- per-step output FC: out[t+1,b,n] = h1[b,n,:] . Wfc + bfc ------
__global__ void k_out(float* __restrict__ out, const float* __restrict__ Wfc,
                      const float* __restrict__ bfc, int t) {
    int gw = (blockIdx.x * blockDim.x + threadIdx.x) >> 5;
    int lane = threadIdx.x & 31;
    if (gw >= BB*NN) return;
    int b = gw / NN, n = gw - b*NN;
    const float* h = g_h[1] + (long)b*NH + n*HID;
    float s = h[lane]*Wfc[lane] + h[lane + 32]*Wfc[lane + 32];
#pragma unroll
    for (int o = 16; o; o >>= 1) s += __shfl_down_sync(0xffffffffu, s, o);
    if (lane == 0) out[(long)(t + 1)*NH + b*NN + n] = s + bfc[0];
}

// ---------------- host orchestration ----------------
extern "C" void kernel_launch(void* const* d_in, const int* in_sizes, int n_in,
                              void* d_out, int out_size) {
    const float* inputs = (const float*)d_in[0];   // [13, 64, 325, 1]
    const float* initst = (const float*)d_in[1];   // [2, 64, 20800]
    const float* adj    = (const float*)d_in[2];   // [325, 325]
    const float* Wg[2]  = { (const float*)d_in[3], (const float*)d_in[7] };
    const float* bg[2]  = { (const float*)d_in[4], (const float*)d_in[8] };
    const float* Wc[2]  = { (const float*)d_in[5], (const float*)d_in[9] };
    const float* bc[2]  = { (const float*)d_in[6], (const float*)d_in[10] };
    const float* Wfc    = (const float*)d_in[11];
    const float* bfc    = (const float*)d_in[12];
    float* out = (float*)d_out;

    k_sums<<<NN, 128>>>(adj);
    k_supports<<<(NN*NN + 255)/256, 256>>>(adj);
    k_copyinit<<<(int)((2*BNH + 255)/256), 256>>>(initst);
    k_zero<<<(NH + 255)/256, 256>>>(out);

    for (int t = 0; t < 12; t++) {
        const float* xin = inputs + (long)t * NH;   // [B, N, 1]
        for (int l = 0; l < 2; l++) {
            int in_dim = l ? HID : 1;
            int C  = in_dim + HID;
            int CB = C * 64;
            int total = NN * CB;
            dim3 gs((CB + 127)/128, (NN + 63)/64, 2);

            // gate gconv -> sigmoid -> r, u
            k_build<<<(total + 255)/256, 256>>>(xin, l, 0, in_dim, C);
            k_smul<false><<<gs, 256>>>(CB);
            k_smul<true ><<<gs, 256>>>(CB);
            k_gemm2<true><<<dim3(NN, 2), 256>>>(C, Wg[l], bg[l], l);

            // candidate gconv (h -> r*h) -> tanh -> GRU state update (in place)
            k_build<<<(total + 255)/256, 256>>>(xin, l, 1, in_dim, C);
            k_smul<false><<<gs, 256>>>(CB);
            k_smul<true ><<<gs, 256>>>(CB);
            k_gemm2<false><<<dim3(NN, 1), 256>>>(C, Wc[l], bc[l], l);
        }
        k_out<<<(BB*NN*32 + 255)/256, 256>>>(out, Wfc, bfc, t);
    }
}

// round 2
// speedup vs baseline: 1.0607x; 1.0607x over previous
#include <cuda_runtime.h>
#include <math.h>

// ---------------- problem constants ----------------
#define NN    325
#define NR    (4*NN)           // 1300 stacked operator rows
#define HID   64
#define BB    64
#define NH    (NN*HID)         // 20800 (== BB*NN, coincidence used for out indexing)
#define BNH   ((long)BB*NH)
#define MAXCB (128*64)         // 8192

// ---------------- device scratch ----------------
__device__ float g_S[2][NN*NN];
__device__ float g_SS[4L*NN*NN];            // [S1; 2S1^2-I; S2; 2S2^2-I], row-major 1300x325
__device__ float g_rsum[NN];
__device__ float g_csum[NN];
__device__ float g_mats[5L * NN * MAXCB];   // mats[m][n][c][b], b fastest; rows of m=1..4 contiguous
__device__ float g_h[2][BNH];
__device__ float g_u[BNH];

// ---------------- support prep ----------------
__global__ void k_sums(const float* __restrict__ adj) {
    __shared__ float sr[128], sc[128];
    int i = blockIdx.x;
    float rs = 0.f, cs = 0.f;
    for (int j = threadIdx.x; j < NN; j += 128) {
        rs += adj[i*NN + j];
        cs += adj[j*NN + i];
    }
    sr[threadIdx.x] = rs; sc[threadIdx.x] = cs;
    __syncthreads();
    for (int o = 64; o; o >>= 1) {
        if (threadIdx.x < o) {
            sr[threadIdx.x] += sr[threadIdx.x + o];
            sc[threadIdx.x] += sc[threadIdx.x + o];
        }
        __syncthreads();
    }
    if (threadIdx.x == 0) { g_rsum[i] = sr[0]; g_csum[i] = sc[0]; }
}

__global__ void k_supports(const float* __restrict__ adj) {
    int idx = blockIdx.x * blockDim.x + threadIdx.x;
    if (idx >= NN*NN) return;
    int i = idx / NN, j = idx - i*NN;
    float s1 = adj[j*NN + i] / g_rsum[j];   // S1 = (A/rowsum).T
    float s2 = adj[idx]      / g_csum[j];   // S2 = (A.T/rowsum(A.T)).T
    g_S[0][idx] = s1;
    g_S[1][idx] = s2;
    g_SS[0L*NN*NN + idx] = s1;              // stacked slot m=1
    g_SS[2L*NN*NN + idx] = s2;              // stacked slot m=3
}

// C = 2*A@A - I  into stacked slots 1 and 3 (m=2, m=4)
__global__ void k_chsq() {
    int z = blockIdx.z;
    const float* __restrict__ A = g_S[z];
    float* __restrict__ C = g_SS + (long)(2*z + 1)*NN*NN;
    __shared__ float At[16][16], Bt[16][17];
    int ty = threadIdx.y, tx = threadIdx.x;
    int i = blockIdx.y*16 + ty, j = blockIdx.x*16 + tx;
    float s = 0.f;
    for (int kt = 0; kt < NN; kt += 16) {
        At[ty][tx] = (i < NN && kt + tx < NN) ? A[i*NN + kt + tx] : 0.f;
        Bt[ty][tx] = (kt + ty < NN && j < NN) ? A[(kt + ty)*NN + j] : 0.f;
        __syncthreads();
#pragma unroll
        for (int k = 0; k < 16; k++) s += At[ty][k] * Bt[k][tx];
        __syncthreads();
    }
    if (i < NN && j < NN) C[i*NN + j] = 2.f*s - (i == j ? 1.f : 0.f);
}

__global__ void k_copyinit(const float* __restrict__ s) {
    long i = (long)blockIdx.x * blockDim.x + threadIdx.x;
    if (i < 2*BNH) (&g_h[0][0])[i] = s[i];
}

__global__ void k_zero(float* __restrict__ out) {
    int i = blockIdx.x * blockDim.x + threadIdx.x;
    if (i < NH) out[i] = 0.f;
}

// ---------------- build x0 = [x | h] in [n][c][b] layout (gate only) --------
__global__ void k_build(const float* __restrict__ x_ext, int layer, int in_dim, int C) {
    int idx = blockIdx.x * blockDim.x + threadIdx.x;
    int total = NN * C * 64;
    if (idx >= total) return;
    int b = idx & 63;
    int c = (idx >> 6) % C;
    int n = idx / (C * 64);
    float v;
    if (c < in_dim) {
        v = (layer == 0) ? x_ext[b*NN + n] : g_h[0][(long)b*NH + n*HID + c];
    } else {
        v = g_h[layer][(long)b*NH + n*HID + (c - in_dim)];
    }
    g_mats[idx] = v;
}

// ---------------- Y[1300, W] = SS @ x0   (columns [col0, col0+W) of the CBfull matrix)
// 64x256 tile, BK=16, 256 threads, 8x8 per thread, reg double-buffered.
__global__ __launch_bounds__(256) void k_smulB(int CBfull, int col0, int W) {
    const long MS = (long)NN * CBfull;
    const float* __restrict__ X = g_mats;          // x0 rows
    float* __restrict__ Y = g_mats + MS;           // stacked rows (mats 1..4)

    const int m0 = blockIdx.y * 64;
    const int n0 = blockIdx.x * 256;
    const int tid  = threadIdx.x;
    const int warp = tid >> 5, lane = tid & 31;

    __shared__ float As[16][64];
    __shared__ float Bs[16][256];

    float acc[8][8];
#pragma unroll
    for (int i = 0; i < 8; i++)
#pragma unroll
        for (int j = 0; j < 8; j++) acc[i][j] = 0.f;

    const int lm  = tid & 63;          // As: m index
    const int lk4 = (tid >> 6) << 2;   // As: k base
    const int bkr = tid >> 4;          // Bs: k row
    const int bc0 = (tid & 15) << 4;   // Bs: col base (16 floats)

    float  pa[4];
    float4 pb[4];

    auto ldtile = [&](int kt) {
        int gm = m0 + lm;
#pragma unroll
        for (int i = 0; i < 4; i++) {
            int gk = kt + lk4 + i;
            pa[i] = (gm < NR && gk < NN) ? g_SS[(long)gm*NN + gk] : 0.f;
        }
        int gk = kt + bkr;
        bool ok = (gk < NN) && ((n0 + bc0) < W);
        const float* src = X + (long)gk*CBfull + col0 + n0 + bc0;
#pragma unroll
        for (int q = 0; q < 4; q++)
            pb[q] = ok ? *(const float4*)(src + 4*q) : make_float4(0.f,0.f,0.f,0.f);
    };

    ldtile(0);
    for (int kt = 0; kt < NN; kt += 16) {
#pragma unroll
        for (int i = 0; i < 4; i++) As[lk4 + i][lm] = pa[i];
#pragma unroll
        for (int q = 0; q < 4; q++) *(float4*)&Bs[bkr][bc0 + 4*q] = pb[q];
        __syncthreads();
        if (kt + 16 < NN) ldtile(kt + 16);
#pragma unroll
        for (int k = 0; k < 16; k++) {
            float4 A0 = *(const float4*)&As[k][warp*8];
            float4 A1 = *(const float4*)&As[k][warp*8 + 4];
            float4 W0 = *(const float4*)&Bs[k][lane*8];
            float4 W1 = *(const float4*)&Bs[k][lane*8 + 4];
            float a[8] = {A0.x,A0.y,A0.z,A0.w,A1.x,A1.y,A1.z,A1.w};
            float w[8] = {W0.x,W0.y,W0.z,W0.w,W1.x,W1.y,W1.z,W1.w};
#pragma unroll
            for (int i = 0; i < 8; i++)
#pragma unroll
                for (int j = 0; j < 8; j++)
                    acc[i][j] += a[i] * w[j];
        }
        __syncthreads();
    }

    int jc0 = n0 + lane*8;
    if (jc0 < W) {
#pragma unroll
        for (int i = 0; i < 8; i++) {
            int gm = m0 + warp*8 + i;
            if (gm >= NR) continue;
            float* yp = Y + (long)gm*CBfull + col0 + jc0;
            *(float4*)(yp)     = make_float4(acc[i][0], acc[i][1], acc[i][2], acc[i][3]);
            *(float4*)(yp + 4) = make_float4(acc[i][4], acc[i][5], acc[i][6], acc[i][7]);
        }
    }
}

// ---------------- per-node GEMM2: xs @ W + b, fused epilogues --------------
// Block = node n, 128 threads = 4 warps. Warp w owns b-rows [w*16, w*16+16).
// Lane owns CPT output columns. GATE: sigmoid; r fused into mats0 h-cols (r*h),
// u stored. !GATE: tanh + GRU update; optional fused output FC (layer 1).
template<bool GATE, bool FUSE>
__global__ __launch_bounds__(128) void k_gemm2(
        int C, int in_dim, const float* __restrict__ Wm, const float* __restrict__ bias,
        int layer, float* __restrict__ out, const float* __restrict__ Wfc,
        const float* __restrict__ bfc, int t) {
    constexpr int OW  = GATE ? 128 : 64;
    constexpr int CPT = GATE ? 4 : 2;
    const int n = blockIdx.x;
    const int CBfull = C * 64;
    const long MS = (long)NN * CBfull;
    const int tid = threadIdx.x, w = tid >> 5, lane = tid & 31;

    __shared__ float Axs[20][64];
    __shared__ float Ws[20][128];

    float acc[16][CPT];
#pragma unroll
    for (int i = 0; i < 16; i++)
#pragma unroll
        for (int j = 0; j < CPT; j++) acc[i][j] = 0.f;

    const int ntiles = (C + 3) >> 2;
    for (int ct = 0; ct < ntiles; ct++) {
        int c0 = ct * 4;
#pragma unroll
        for (int r = 0; r < 10; r++) {                 // 1280 / 128
            int e = tid + r*128;
            int lo = e & 63, km = e >> 6;
            int cq = km / 5, m = km - 5*cq;
            int c = c0 + cq;
            Axs[km][lo] = (c < C)
                ? g_mats[(long)m*MS + (long)n*CBfull + (long)c*64 + lo] : 0.f;
        }
        constexpr int NW = (20*OW) / 128;
#pragma unroll
        for (int r = 0; r < NW; r++) {
            int e = tid + r*128;
            int col = e % OW, km = e / OW;
            int cq = km / 5, m = km - 5*cq;
            int c = c0 + cq;
            Ws[km][col] = (c < C) ? Wm[(long)(c*5 + m)*OW + col] : 0.f;
        }
        __syncthreads();
#pragma unroll
        for (int km = 0; km < 20; km++) {
            const float* ar = &Axs[km][w*16];
            float4 A0 = *(const float4*)(ar);
            float4 A1 = *(const float4*)(ar + 4);
            float4 A2 = *(const float4*)(ar + 8);
            float4 A3 = *(const float4*)(ar + 12);
            float af[16] = {A0.x,A0.y,A0.z,A0.w, A1.x,A1.y,A1.z,A1.w,
                            A2.x,A2.y,A2.z,A2.w, A3.x,A3.y,A3.z,A3.w};
            float wv[CPT];
            if (GATE) {
                float4 Wq = *(const float4*)&Ws[km][lane*4];
                wv[0]=Wq.x; wv[1]=Wq.y; wv[2]=Wq.z; wv[3]=Wq.w;
            } else {
                float2 Wq = *(const float2*)&Ws[km][lane*2];
                wv[0]=Wq.x; wv[1]=Wq.y;
            }
#pragma unroll
            for (int i = 0; i < 16; i++)
#pragma unroll
                for (int j = 0; j < CPT; j++)
                    acc[i][j] += af[i] * wv[j];
        }
        __syncthreads();
    }

#pragma unroll
    for (int i = 0; i < 16; i++) {
        int b = w*16 + i;
        long off = (long)b*NH + n*HID;
        if (GATE) {
#pragma unroll
            for (int j = 0; j < CPT; j++) {
                int ol = lane*CPT + j;
                float v = acc[i][j] + bias[ol];
                v = 1.f / (1.f + __expf(-v));
                if (ol < 64) {
                    // r fused: write x0 h-column = r * h  (candidate build)
                    g_mats[(long)n*CBfull + (long)(in_dim + ol)*64 + b] =
                        v * g_h[layer][off + ol];
                } else {
                    g_u[off + (ol - 64)] = v;
                }
            }
        } else {
            float s = 0.f;
#pragma unroll
            for (int j = 0; j < CPT; j++) {
                int ol = lane*CPT + j;
                float cv = tanhf(acc[i][j] + bias[ol]);
                float u  = g_u[off + ol];
                float h  = g_h[layer][off + ol];
                float hn = u*h + (1.f - u)*cv;
                g_h[layer][off + ol] = hn;
                if (FUSE) s += hn * Wfc[ol];
            }
            if (FUSE) {
#pragma unroll
                for (int o = 16; o; o >>= 1) s += __shfl_down_sync(0xffffffffu, s, o);
                if (lane == 0)
                    out[(long)(t + 1)*NH + b*NN + n] = s + bfc[0];
            }
        }
    }
}

// ---------------- host orchestration ----------------
extern "C" void kernel_launch(void* const* d_in, const int* in_sizes, int n_in,
                              void* d_out, int out_size) {
    const float* inputs = (const float*)d_in[0];   // [13, 64, 325, 1]
    const float* initst = (const float*)d_in[1];   // [2, 64, 20800]
    const float* adj    = (const float*)d_in[2];   // [325, 325]
    const float* Wg[2]  = { (const float*)d_in[3], (const float*)d_in[7] };
    const float* bg[2]  = { (const float*)d_in[4], (const float*)d_in[8] };
    const float* Wc[2]  = { (const float*)d_in[5], (const float*)d_in[9] };
    const float* bc[2]  = { (const float*)d_in[6], (const float*)d_in[10] };
    const float* Wfc    = (const float*)d_in[11];
    const float* bfc    = (const float*)d_in[12];
    float* out = (float*)d_out;

    k_sums<<<NN, 128>>>(adj);
    k_supports<<<(NN*NN + 255)/256, 256>>>(adj);
    {
        dim3 b(16,16), g((NN+15)/16, (NN+15)/16, 2);
        k_chsq<<<g, b>>>();
    }
    k_copyinit<<<(int)((2*BNH + 255)/256), 256>>>(initst);
    k_zero<<<(NH + 255)/256, 256>>>(out);

    const int YB = (NR + 63)/64;   // 21
    for (int t = 0; t < 12; t++) {
        const float* xin = inputs + (long)t * NH;
        for (int l = 0; l < 2; l++) {
            int in_dim = l ? HID : 1;
            int C  = in_dim + HID;
            int CB = C * 64;

            // gate gconv
            k_build<<<(NN*CB + 255)/256, 256>>>(xin, l, in_dim, C);
            k_smulB<<<dim3((CB + 255)/256, YB), 256>>>(CB, 0, CB);
            k_gemm2<true, false><<<NN, 128>>>(C, in_dim, Wg[l], bg[l], l,
                                              nullptr, nullptr, nullptr, 0);

            // candidate gconv: only h-columns recomputed (r*h written by gate epilogue)
            k_smulB<<<dim3(16, YB), 256>>>(CB, in_dim*64, 4096);
            if (l == 1)
                k_gemm2<false, true><<<NN, 128>>>(C, in_dim, Wc[l], bc[l], l,
                                                  out, Wfc, bfc, t);
            else
                k_gemm2<false, false><<<NN, 128>>>(C, in_dim, Wc[l], bc[l], l,
                                                   nullptr, nullptr, nullptr, 0);
        }
    }
}